// round 6
// baseline (speedup 1.0000x reference)
#include <cuda_runtime.h>

#define IC 1152
#define OC 10
#define ID 8
#define OD 16
#define BATCH 32
#define NI 8
#define NBLK (IC / NI)     // 144
#define THREADS 640        // 20 warps: thread = (c, b, od_half)
#define OUTSZ (BATCH * OC * OD)   // 5120
#define EPB 36             // output elements reduced per block (144*36 >= 5120)

typedef unsigned long long ull;

__device__ float g_scratch[NBLK * OUTSZ];   // per-block partial outputs
__device__ int g_arrive;                    // zero-init; reset each launch
__device__ int g_done;

__device__ __forceinline__ ull ffma2(ull a, ull b, ull c) {
    ull d; asm("fma.rn.f32x2 %0, %1, %2, %3;" : "=l"(d) : "l"(a), "l"(b), "l"(c)); return d;
}
__device__ __forceinline__ ull fmul2(ull a, ull b) {
    ull d; asm("mul.rn.f32x2 %0, %1, %2;" : "=l"(d) : "l"(a), "l"(b)); return d;
}
__device__ __forceinline__ ull fadd2(ull a, ull b) {
    ull d; asm("add.rn.f32x2 %0, %1, %2;" : "=l"(d) : "l"(a), "l"(b)); return d;
}
__device__ __forceinline__ ull pack2(float x, float y) {
    ull u; asm("mov.b64 %0, {%1, %2};" : "=l"(u) : "f"(x), "f"(y)); return u;
}
__device__ __forceinline__ void unpack2(ull u, float& x, float& y) {
    asm("mov.b64 {%0, %1}, %2;" : "=f"(x), "=f"(y) : "l"(u));
}
__device__ __forceinline__ float frcp(float x) {
    float y; asm("rcp.approx.f32 %0, %1;" : "=f"(y) : "f"(x)); return y;
}

__global__ __launch_bounds__(THREADS, 1) void caps_kernel(
    const float* __restrict__ x, const float* __restrict__ w, float* __restrict__ out)
{
    __shared__ __align__(16) float ws_sm[2][OC * ID * OD];  // double-buffered ŵ
    __shared__ float wsum_sm[2][OC * ID];
    __shared__ float xn_sm[2][ID][BATCH];
    __shared__ float alpha_sm[OC * BATCH];

    const int t   = threadIdx.x;
    const int c   = t >> 6;          // output capsule: 2 warps per c
    const int b   = (t & 63) >> 1;   // batch
    const int odh = t & 1;           // od half
    const int i0  = blockIdx.x * NI;

    // ---- prefetch first i ----
    float2 wv = *(const float2*)(w + (size_t)i0 * (OC * ID * OD) + t * 2);
    float4 xv = make_float4(0.f, 0.f, 0.f, 0.f);
    if (t < 2 * BATCH) {
        int bb = t >> 1, half = t & 1;
        xv = *(const float4*)(x + ((size_t)bb * IC + i0) * ID + half * 4);
    }

    ull acc[4];
    #pragma unroll
    for (int j = 0; j < 4; j++) acc[j] = pack2(0.f, 0.f);

    #pragma unroll 1
    for (int ii = 0; ii < NI; ii++) {
        const int p = ii & 1;
        // ---- stage weights: each thread holds 2 od-values of row (c,d) = t/8 ----
        {
            float ps  = wv.x + wv.y;
            float tot = ps + __shfl_xor_sync(0xffffffffu, ps, 1);
            tot += __shfl_xor_sync(0xffffffffu, tot, 2);
            tot += __shfl_xor_sync(0xffffffffu, tot, 4);
            float r = frcp(tot);
            float2 wn; wn.x = wv.x * r; wn.y = wv.y * r;
            *(float2*)(&ws_sm[p][0] + t * 2) = wn;
            if ((t & 7) == 0) wsum_sm[p][t >> 3] = tot;
        }
        // ---- stage x: normalize over id, transpose to [d][b] ----
        if (t < 2 * BATCH) {
            int bb = t >> 1, half = t & 1;
            float ps  = xv.x + xv.y + xv.z + xv.w;
            float tot = ps + __shfl_xor_sync(0xffffffffu, ps, 1);
            float r = frcp(tot);
            xn_sm[p][half * 4 + 0][bb] = xv.x * r;
            xn_sm[p][half * 4 + 1][bb] = xv.y * r;
            xn_sm[p][half * 4 + 2][bb] = xv.z * r;
            xn_sm[p][half * 4 + 3][bb] = xv.w * r;
        }
        __syncthreads();   // sync#1: staging visible

        // ---- prefetch next i ----
        if (ii + 1 < NI) {
            wv = *(const float2*)(w + (size_t)(i0 + ii + 1) * (OC * ID * OD) + t * 2);
            if (t < 2 * BATCH) {
                int bb = t >> 1, half = t & 1;
                xv = *(const float4*)(x + ((size_t)bb * IC + (i0 + ii + 1)) * ID + half * 4);
            }
        }

        const float* wc = &ws_sm[p][0] + c * (ID * OD) + odh * 8;
        float xn[8];
        #pragma unroll
        for (int d = 0; d < 8; d++) xn[d] = xn_sm[p][d][b];

        // ---- iteration 1: h1[o] = Σ_d xn[d]·ŵ[d,o]  (h0 uniform) ----
        ull h[4];
        #pragma unroll
        for (int j = 0; j < 4; j++) h[j] = pack2(0.f, 0.f);
        #pragma unroll
        for (int d = 0; d < 8; d++) {
            ull xp = pack2(xn[d], xn[d]);
            const ulonglong2* wr = (const ulonglong2*)(wc + d * 16);
            ulonglong2 wa = wr[0], wb2 = wr[1];
            h[0] = ffma2(xp, wa.x,  h[0]);
            h[1] = ffma2(xp, wa.y,  h[1]);
            h[2] = ffma2(xp, wb2.x, h[2]);
            h[3] = ffma2(xp, wb2.y, h[3]);
        }

        // ---- iterations 2..5, fused den/f passes (scale-invariant ⇒ no renorm) ----
        #pragma unroll 1
        for (int it = 0; it < 4; it++) {
            ull f[4];
            #pragma unroll
            for (int j = 0; j < 4; j++) f[j] = pack2(0.f, 0.f);
            #pragma unroll
            for (int d = 0; d < 8; d++) {
                const ulonglong2* wr = (const ulonglong2*)(wc + d * 16);
                ulonglong2 wa = wr[0], wb2 = wr[1];
                ull pp = fmul2(h[0], wa.x);
                pp = ffma2(h[1], wa.y, pp);
                ull q = fmul2(h[2], wb2.x);
                q = ffma2(h[3], wb2.y, q);
                pp = fadd2(pp, q);
                float pa, pb; unpack2(pp, pa, pb);
                float hd  = pa + pb;
                float den = hd + __shfl_xor_sync(0xffffffffu, hd, 1);
                float xr  = xn[d] * frcp(den);
                ull xp = pack2(xr, xr);
                f[0] = ffma2(xp, wa.x,  f[0]);
                f[1] = ffma2(xp, wa.y,  f[1]);
                f[2] = ffma2(xp, wb2.x, f[2]);
                f[3] = ffma2(xp, wb2.y, f[3]);
            }
            #pragma unroll
            for (int j = 0; j < 4; j++) h[j] = fmul2(h[j], f[j]);
        }

        // ---- epilogue: alpha from final denominators (reconstruct folded in) ----
        float A = 0.f;
        #pragma unroll
        for (int d = 0; d < 8; d++) {
            const ulonglong2* wr = (const ulonglong2*)(wc + d * 16);
            ulonglong2 wa = wr[0], wb2 = wr[1];
            ull pp = fmul2(h[0], wa.x);
            pp = ffma2(h[1], wa.y, pp);
            ull q = fmul2(h[2], wb2.x);
            q = ffma2(h[3], wb2.y, q);
            pp = fadd2(pp, q);
            float pa, pb; unpack2(pp, pa, pb);
            float hd  = pa + pb;
            float den = hd + __shfl_xor_sync(0xffffffffu, hd, 1);
            A += xn[d] * wsum_sm[p][c * 8 + d] * den;
        }
        ull s2 = fadd2(fadd2(h[0], h[1]), fadd2(h[2], h[3]));
        float sa, sb; unpack2(s2, sa, sb);
        float shh = sa + sb;
        float Sh  = shh + __shfl_xor_sync(0xffffffffu, shh, 1);
        float rSh = frcp(Sh);
        float ar  = A * rSh;
        if (odh == 0) alpha_sm[c * BATCH + b] = ar;
        __syncthreads();   // sync#2: alpha visible (also fences next staging)
        float S = 0.f;
        #pragma unroll
        for (int cc = 0; cc < OC; cc++) S += alpha_sm[cc * BATCH + b];
        float coeff = ar * frcp(S) * rSh;
        ull cp = pack2(coeff, coeff);
        #pragma unroll
        for (int j = 0; j < 4; j++) acc[j] = ffma2(cp, h[j], acc[j]);
        // no loop-end sync: ws/xn double-buffered; alpha protected by sync#1 of next ii
    }

    // ---- per-block partials to scratch (coalesced STG, no atomics) ----
    {
        float* dst = g_scratch + (size_t)blockIdx.x * OUTSZ + b * (OC * OD) + c * OD + odh * 8;
        ulonglong2 s0; s0.x = acc[0]; s0.y = acc[1];
        ulonglong2 s1; s1.x = acc[2]; s1.y = acc[3];
        ((ulonglong2*)dst)[0] = s0;
        ((ulonglong2*)dst)[1] = s1;
    }

    // ---- grid-wide barrier (all 144 blocks co-resident at 1 block/SM) ----
    __threadfence();
    __syncthreads();
    if (t == 0) {
        atomicAdd(&g_arrive, 1);
        while (atomicAdd(&g_arrive, 0) < NBLK) { __nanosleep(64); }
    }
    __syncthreads();

    // ---- fused reduction: block r sums elements [r*EPB, r*EPB+EPB) over 144 partials ----
    if (t < 16 * EPB) {            // 576 threads = 18 full warps
        const int el = t >> 4;     // 0..35
        const int ks = t & 15;     // k-slice
        const int e  = blockIdx.x * EPB + el;
        float s = 0.f;
        if (e < OUTSZ) {
            const float* src = g_scratch + (size_t)ks * OUTSZ + e;
            #pragma unroll
            for (int k = 0; k < 9; k++)      // ks, ks+16, ..., ks+128
                s += __ldcg(src + (size_t)k * 16 * OUTSZ);
        }
        s += __shfl_xor_sync(0xffffffffu, s, 8);
        s += __shfl_xor_sync(0xffffffffu, s, 4);
        s += __shfl_xor_sync(0xffffffffu, s, 2);
        s += __shfl_xor_sync(0xffffffffu, s, 1);
        if (ks == 0 && e < OUTSZ) out[e] = s;
    }

    // ---- reset counters for next launch (graph replay safe: stream-ordered) ----
    __syncthreads();
    if (t == 0) {
        if (atomicAdd(&g_done, 1) == NBLK - 1) {
            g_arrive = 0;
            g_done   = 0;
            __threadfence();
        }
    }
}

extern "C" void kernel_launch(void* const* d_in, const int* in_sizes, int n_in,
                              void* d_out, int out_size)
{
    const float* x = (const float*)d_in[0];
    const float* w = (const float*)d_in[1];
    if (n_in >= 2 && in_sizes[0] == IC * OC * ID * OD && in_sizes[1] == BATCH * IC * ID) {
        x = (const float*)d_in[1];
        w = (const float*)d_in[0];
    }
    float* out = (float*)d_out;

    caps_kernel<<<NBLK, THREADS>>>(x, w, out);
}

// round 7
// speedup vs baseline: 1.0637x; 1.0637x over previous
#include <cuda_runtime.h>

#define IC 1152
#define OC 10
#define ID 8
#define OD 16
#define BATCH 32
#define NI 8
#define NBLK (IC / NI)     // 144
#define THREADS 640        // 20 warps: thread = (c, b, od_half)
#define OUTSZ (BATCH * OC * OD)   // 5120

typedef unsigned long long ull;

__device__ float g_scratch[NBLK * OUTSZ];   // per-block partial outputs

__device__ __forceinline__ ull ffma2(ull a, ull b, ull c) {
    ull d; asm("fma.rn.f32x2 %0, %1, %2, %3;" : "=l"(d) : "l"(a), "l"(b), "l"(c)); return d;
}
__device__ __forceinline__ ull fmul2(ull a, ull b) {
    ull d; asm("mul.rn.f32x2 %0, %1, %2;" : "=l"(d) : "l"(a), "l"(b)); return d;
}
__device__ __forceinline__ ull fadd2(ull a, ull b) {
    ull d; asm("add.rn.f32x2 %0, %1, %2;" : "=l"(d) : "l"(a), "l"(b)); return d;
}
__device__ __forceinline__ ull pack2(float x, float y) {
    ull u; asm("mov.b64 %0, {%1, %2};" : "=l"(u) : "f"(x), "f"(y)); return u;
}
__device__ __forceinline__ void unpack2(ull u, float& x, float& y) {
    asm("mov.b64 {%0, %1}, %2;" : "=f"(x), "=f"(y) : "l"(u));
}
__device__ __forceinline__ float frcp(float x) {
    float y; asm("rcp.approx.f32 %0, %1;" : "=f"(y) : "f"(x)); return y;
}

__global__ __launch_bounds__(THREADS, 1) void caps_kernel(
    const float* __restrict__ x, const float* __restrict__ w, float* __restrict__ out_unused)
{
    __shared__ __align__(16) float ws_sm[2][OC * ID * OD];  // double-buffered ŵ
    __shared__ float wsum_sm[2][OC * ID];
    __shared__ float xn_sm[2][ID][BATCH];
    __shared__ float alpha_sm[OC * BATCH];

    const int t   = threadIdx.x;
    const int c   = t >> 6;          // output capsule: 2 warps per c
    const int b   = (t & 63) >> 1;   // batch
    const int odh = t & 1;           // od half
    const int i0  = blockIdx.x * NI;

    // ---- prefetch first i ----
    float2 wv = *(const float2*)(w + (size_t)i0 * (OC * ID * OD) + t * 2);
    float4 xv = make_float4(0.f, 0.f, 0.f, 0.f);
    if (t < 2 * BATCH) {
        int bb = t >> 1, half = t & 1;
        xv = *(const float4*)(x + ((size_t)bb * IC + i0) * ID + half * 4);
    }

    ull acc[4];
    #pragma unroll
    for (int j = 0; j < 4; j++) acc[j] = pack2(0.f, 0.f);

    #pragma unroll 1
    for (int ii = 0; ii < NI; ii++) {
        const int p = ii & 1;
        // ---- stage weights: each thread holds 2 od-values of row (c,d) = t/8 ----
        {
            float ps  = wv.x + wv.y;
            float tot = ps + __shfl_xor_sync(0xffffffffu, ps, 1);
            tot += __shfl_xor_sync(0xffffffffu, tot, 2);
            tot += __shfl_xor_sync(0xffffffffu, tot, 4);
            float r = frcp(tot);
            float2 wn; wn.x = wv.x * r; wn.y = wv.y * r;
            *(float2*)(&ws_sm[p][0] + t * 2) = wn;
            if ((t & 7) == 0) wsum_sm[p][t >> 3] = tot;
        }
        // ---- stage x: normalize over id, transpose to [d][b] ----
        if (t < 2 * BATCH) {
            int bb = t >> 1, half = t & 1;
            float ps  = xv.x + xv.y + xv.z + xv.w;
            float tot = ps + __shfl_xor_sync(0xffffffffu, ps, 1);
            float r = frcp(tot);
            xn_sm[p][half * 4 + 0][bb] = xv.x * r;
            xn_sm[p][half * 4 + 1][bb] = xv.y * r;
            xn_sm[p][half * 4 + 2][bb] = xv.z * r;
            xn_sm[p][half * 4 + 3][bb] = xv.w * r;
        }
        __syncthreads();   // sync#1: staging visible

        // ---- prefetch next i ----
        if (ii + 1 < NI) {
            wv = *(const float2*)(w + (size_t)(i0 + ii + 1) * (OC * ID * OD) + t * 2);
            if (t < 2 * BATCH) {
                int bb = t >> 1, half = t & 1;
                xv = *(const float4*)(x + ((size_t)bb * IC + (i0 + ii + 1)) * ID + half * 4);
            }
        }

        const float* wc = &ws_sm[p][0] + c * (ID * OD) + odh * 8;
        float xn[8];
        #pragma unroll
        for (int d = 0; d < 8; d++) xn[d] = xn_sm[p][d][b];

        // ---- iteration 1: h1[o] = Σ_d xn[d]·ŵ[d,o]  (h0 uniform) ----
        ull h[4];
        #pragma unroll
        for (int j = 0; j < 4; j++) h[j] = pack2(0.f, 0.f);
        #pragma unroll
        for (int d = 0; d < 8; d++) {
            ull xp = pack2(xn[d], xn[d]);
            const ulonglong2* wr = (const ulonglong2*)(wc + d * 16);
            ulonglong2 wa = wr[0], wb2 = wr[1];
            h[0] = ffma2(xp, wa.x,  h[0]);
            h[1] = ffma2(xp, wa.y,  h[1]);
            h[2] = ffma2(xp, wb2.x, h[2]);
            h[3] = ffma2(xp, wb2.y, h[3]);
        }

        // ---- iterations 2..5, fused den/f passes (scale-invariant ⇒ no renorm) ----
        #pragma unroll 1
        for (int it = 0; it < 4; it++) {
            ull f[4];
            #pragma unroll
            for (int j = 0; j < 4; j++) f[j] = pack2(0.f, 0.f);
            #pragma unroll
            for (int d = 0; d < 8; d++) {
                const ulonglong2* wr = (const ulonglong2*)(wc + d * 16);
                ulonglong2 wa = wr[0], wb2 = wr[1];
                ull pp = fmul2(h[0], wa.x);
                pp = ffma2(h[1], wa.y, pp);
                ull q = fmul2(h[2], wb2.x);
                q = ffma2(h[3], wb2.y, q);
                pp = fadd2(pp, q);
                float pa, pb; unpack2(pp, pa, pb);
                float hd  = pa + pb;
                float den = hd + __shfl_xor_sync(0xffffffffu, hd, 1);
                float xr  = xn[d] * frcp(den);
                ull xp = pack2(xr, xr);
                f[0] = ffma2(xp, wa.x,  f[0]);
                f[1] = ffma2(xp, wa.y,  f[1]);
                f[2] = ffma2(xp, wb2.x, f[2]);
                f[3] = ffma2(xp, wb2.y, f[3]);
            }
            #pragma unroll
            for (int j = 0; j < 4; j++) h[j] = fmul2(h[j], f[j]);
        }

        // ---- epilogue: alpha from final denominators (reconstruct folded in) ----
        float A = 0.f;
        #pragma unroll
        for (int d = 0; d < 8; d++) {
            const ulonglong2* wr = (const ulonglong2*)(wc + d * 16);
            ulonglong2 wa = wr[0], wb2 = wr[1];
            ull pp = fmul2(h[0], wa.x);
            pp = ffma2(h[1], wa.y, pp);
            ull q = fmul2(h[2], wb2.x);
            q = ffma2(h[3], wb2.y, q);
            pp = fadd2(pp, q);
            float pa, pb; unpack2(pp, pa, pb);
            float hd  = pa + pb;
            float den = hd + __shfl_xor_sync(0xffffffffu, hd, 1);
            A += xn[d] * wsum_sm[p][c * 8 + d] * den;
        }
        ull s2 = fadd2(fadd2(h[0], h[1]), fadd2(h[2], h[3]));
        float sa, sb; unpack2(s2, sa, sb);
        float shh = sa + sb;
        float Sh  = shh + __shfl_xor_sync(0xffffffffu, shh, 1);
        float rSh = frcp(Sh);
        float ar  = A * rSh;
        if (odh == 0) alpha_sm[c * BATCH + b] = ar;
        __syncthreads();   // sync#2: alpha visible (also fences next staging writes)
        float S = 0.f;
        #pragma unroll
        for (int cc = 0; cc < OC; cc++) S += alpha_sm[cc * BATCH + b];
        float coeff = ar * frcp(S) * rSh;
        ull cp = pack2(coeff, coeff);
        #pragma unroll
        for (int j = 0; j < 4; j++) acc[j] = ffma2(cp, h[j], acc[j]);
        // no loop-end sync: ws/xn double-buffered; alpha_sm protected by next sync#1... 
        // (alpha_sm is read above and only rewritten after the NEXT sync#2, so safe)
    }

    // ---- per-block partials to scratch (coalesced STG, no atomics) ----
    float* dst = g_scratch + (size_t)blockIdx.x * OUTSZ + b * (OC * OD) + c * OD + odh * 8;
    ulonglong2 s0; s0.x = acc[0]; s0.y = acc[1];
    ulonglong2 s1; s1.x = acc[2]; s1.y = acc[3];
    ((ulonglong2*)dst)[0] = s0;
    ((ulonglong2*)dst)[1] = s1;
}

// Reduce v3: 160 blocks x 512 threads. warp = k-slice (16 slices x 9 loads),
// lane = output index within the block's 32-element chunk. All loads are
// 128B-coalesced per warp and L2-resident (scratch just written). MLP=9/thread,
// 16 warps/block -> latency fully hidden.
__global__ __launch_bounds__(512, 1) void caps_reduce_kernel(float* __restrict__ out) {
    __shared__ float red[16][32];
    const int lane = threadIdx.x & 31;
    const int ks   = threadIdx.x >> 5;         // 0..15
    const int j    = blockIdx.x * 32 + lane;   // output index (5120 total)

    const float* src = g_scratch + (size_t)ks * OUTSZ + j;
    float s = 0.f;
    #pragma unroll
    for (int k = 0; k < 9; k++)                // ks, ks+16, ..., ks+128
        s += __ldcg(src + (size_t)k * 16 * OUTSZ);

    red[ks][lane] = s;
    __syncthreads();
    if (ks == 0) {
        float acc = 0.f;
        #pragma unroll
        for (int q = 0; q < 16; q++) acc += red[q][lane];
        out[j] = acc;
    }
}

extern "C" void kernel_launch(void* const* d_in, const int* in_sizes, int n_in,
                              void* d_out, int out_size)
{
    const float* x = (const float*)d_in[0];
    const float* w = (const float*)d_in[1];
    if (n_in >= 2 && in_sizes[0] == IC * OC * ID * OD && in_sizes[1] == BATCH * IC * ID) {
        x = (const float*)d_in[1];
        w = (const float*)d_in[0];
    }
    float* out = (float*)d_out;

    caps_kernel<<<NBLK, THREADS>>>(x, w, out);
    caps_reduce_kernel<<<OUTSZ / 32, 512>>>(out);
}

// round 8
// speedup vs baseline: 1.1322x; 1.0643x over previous
#include <cuda_runtime.h>

#define IC 1152
#define OC 10
#define ID 8
#define OD 16
#define BATCH 32
#define NI 8
#define NBLK (IC / NI)     // 144
#define THREADS 640        // 20 warps: thread = (c, b, od_half)
#define OUTSZ (BATCH * OC * OD)   // 5120
#define WROW (OC * ID)     // 80 weight rows (of 16 floats) per i

typedef unsigned long long ull;

__device__ float g_scratch[NBLK * OUTSZ];   // per-block partial outputs

__device__ __forceinline__ ull ffma2(ull a, ull b, ull c) {
    ull d; asm("fma.rn.f32x2 %0, %1, %2, %3;" : "=l"(d) : "l"(a), "l"(b), "l"(c)); return d;
}
__device__ __forceinline__ ull fmul2(ull a, ull b) {
    ull d; asm("mul.rn.f32x2 %0, %1, %2;" : "=l"(d) : "l"(a), "l"(b)); return d;
}
__device__ __forceinline__ ull fadd2(ull a, ull b) {
    ull d; asm("add.rn.f32x2 %0, %1, %2;" : "=l"(d) : "l"(a), "l"(b)); return d;
}
__device__ __forceinline__ ull pack2(float x, float y) {
    ull u; asm("mov.b64 %0, {%1, %2};" : "=l"(u) : "f"(x), "f"(y)); return u;
}
__device__ __forceinline__ void unpack2(ull u, float& x, float& y) {
    asm("mov.b64 {%0, %1}, %2;" : "=f"(x), "=f"(y) : "l"(u));
}
__device__ __forceinline__ float frcp(float x) {
    float y; asm("rcp.approx.f32 %0, %1;" : "=f"(y) : "f"(x)); return y;
}

__global__ __launch_bounds__(THREADS, 1) void caps_kernel(
    const float* __restrict__ x, const float* __restrict__ w, float* __restrict__ out_unused)
{
    __shared__ __align__(16) float ws_sm[NI * OC * ID * OD];  // 10240 f = 40KB, all 8 i's
    __shared__ float wsum_sm[NI * WROW];                      // 640 f
    __shared__ float xn_sm[NI][ID][BATCH + 1];                // padded: conflict-free transpose
    __shared__ float alpha_sm[2][OC * BATCH];

    const int t   = threadIdx.x;
    const int c   = t >> 6;          // output capsule: 2 warps per c
    const int b   = (t & 63) >> 1;   // batch
    const int odh = t & 1;           // od half
    const int i0  = blockIdx.x * NI;

    // ==== stage ALL weights: thread t owns row (ii,c,d)=t; full 16-od row in-thread ====
    {
        const float4* wr = (const float4*)(w + ((size_t)i0 * WROW + t) * OD);
        float4 a0 = wr[0], a1 = wr[1], a2 = wr[2], a3 = wr[3];
        float tot = (a0.x + a0.y + a0.z + a0.w) + (a1.x + a1.y + a1.z + a1.w)
                  + (a2.x + a2.y + a2.z + a2.w) + (a3.x + a3.y + a3.z + a3.w);
        float r = frcp(tot);
        float4* dst = (float4*)(ws_sm + t * OD);
        float4 s0, s1, s2, s3;
        s0.x = a0.x * r; s0.y = a0.y * r; s0.z = a0.z * r; s0.w = a0.w * r;
        s1.x = a1.x * r; s1.y = a1.y * r; s1.z = a1.z * r; s1.w = a1.w * r;
        s2.x = a2.x * r; s2.y = a2.y * r; s2.z = a2.z * r; s2.w = a2.w * r;
        s3.x = a3.x * r; s3.y = a3.y * r; s3.z = a3.z * r; s3.w = a3.w * r;
        dst[0] = s0; dst[1] = s1; dst[2] = s2; dst[3] = s3;
        wsum_sm[t] = tot;
    }
    // ==== stage ALL x: t<512: thread = (b, q) with q = (ii, d-half); 1 shfl per thread ====
    if (t < 512) {
        int bb = t >> 4, q = t & 15;
        float4 xv = *(const float4*)(x + (size_t)bb * (IC * ID) + (size_t)i0 * ID + q * 4);
        float ps  = xv.x + xv.y + xv.z + xv.w;
        float tot = ps + __shfl_xor_sync(0xffffffffu, ps, 1);
        float r = frcp(tot);
        int ii = q >> 1, dh = (q & 1) * 4;
        xn_sm[ii][dh + 0][bb] = xv.x * r;
        xn_sm[ii][dh + 1][bb] = xv.y * r;
        xn_sm[ii][dh + 2][bb] = xv.z * r;
        xn_sm[ii][dh + 3][bb] = xv.w * r;
    }
    __syncthreads();   // the ONLY staging barrier

    ull acc[4];
    #pragma unroll
    for (int j = 0; j < 4; j++) acc[j] = pack2(0.f, 0.f);

    #pragma unroll 1
    for (int ii = 0; ii < NI; ii++) {
        const int p = ii & 1;
        const float* wc = ws_sm + ii * (OC * ID * OD) + c * (ID * OD) + odh * 8;
        float xn[8];
        #pragma unroll
        for (int d = 0; d < 8; d++) xn[d] = xn_sm[ii][d][b];

        // ---- iteration 1: h1[o] = Σ_d xn[d]·ŵ[d,o]  (h0 uniform) ----
        ull h[4];
        #pragma unroll
        for (int j = 0; j < 4; j++) h[j] = pack2(0.f, 0.f);
        #pragma unroll
        for (int d = 0; d < 8; d++) {
            ull xp = pack2(xn[d], xn[d]);
            const ulonglong2* wr = (const ulonglong2*)(wc + d * 16);
            ulonglong2 wa = wr[0], wb2 = wr[1];
            h[0] = ffma2(xp, wa.x,  h[0]);
            h[1] = ffma2(xp, wa.y,  h[1]);
            h[2] = ffma2(xp, wb2.x, h[2]);
            h[3] = ffma2(xp, wb2.y, h[3]);
        }

        // ---- iterations 2..5, fused den/f passes (scale-invariant ⇒ no renorm) ----
        #pragma unroll 1
        for (int it = 0; it < 4; it++) {
            ull f[4];
            #pragma unroll
            for (int j = 0; j < 4; j++) f[j] = pack2(0.f, 0.f);
            #pragma unroll
            for (int d = 0; d < 8; d++) {
                const ulonglong2* wr = (const ulonglong2*)(wc + d * 16);
                ulonglong2 wa = wr[0], wb2 = wr[1];
                ull pp = fmul2(h[0], wa.x);
                pp = ffma2(h[1], wa.y, pp);
                ull q = fmul2(h[2], wb2.x);
                q = ffma2(h[3], wb2.y, q);
                pp = fadd2(pp, q);
                float pa, pb; unpack2(pp, pa, pb);
                float hd  = pa + pb;
                float den = hd + __shfl_xor_sync(0xffffffffu, hd, 1);
                float xr  = xn[d] * frcp(den);
                ull xp = pack2(xr, xr);
                f[0] = ffma2(xp, wa.x,  f[0]);
                f[1] = ffma2(xp, wa.y,  f[1]);
                f[2] = ffma2(xp, wb2.x, f[2]);
                f[3] = ffma2(xp, wb2.y, f[3]);
            }
            #pragma unroll
            for (int j = 0; j < 4; j++) h[j] = fmul2(h[j], f[j]);
        }

        // ---- epilogue: alpha from final denominators (reconstruct folded in) ----
        float A = 0.f;
        #pragma unroll
        for (int d = 0; d < 8; d++) {
            const ulonglong2* wr = (const ulonglong2*)(wc + d * 16);
            ulonglong2 wa = wr[0], wb2 = wr[1];
            ull pp = fmul2(h[0], wa.x);
            pp = ffma2(h[1], wa.y, pp);
            ull q = fmul2(h[2], wb2.x);
            q = ffma2(h[3], wb2.y, q);
            pp = fadd2(pp, q);
            float pa, pb; unpack2(pp, pa, pb);
            float hd  = pa + pb;
            float den = hd + __shfl_xor_sync(0xffffffffu, hd, 1);
            A += xn[d] * wsum_sm[ii * WROW + c * 8 + d] * den;
        }
        ull s2 = fadd2(fadd2(h[0], h[1]), fadd2(h[2], h[3]));
        float sa, sb; unpack2(s2, sa, sb);
        float shh = sa + sb;
        float Sh  = shh + __shfl_xor_sync(0xffffffffu, shh, 1);
        float rSh = frcp(Sh);
        float ar  = A * rSh;
        if (odh == 0) alpha_sm[p][c * BATCH + b] = ar;
        __syncthreads();   // the only per-ii barrier: alpha visibility
        float S = 0.f;
        #pragma unroll
        for (int cc = 0; cc < OC; cc++) S += alpha_sm[p][cc * BATCH + b];
        float coeff = ar * frcp(S) * rSh;
        ull cp = pack2(coeff, coeff);
        #pragma unroll
        for (int j = 0; j < 4; j++) acc[j] = ffma2(cp, h[j], acc[j]);
        // alpha_sm[p] rewritten at ii+2, which is after sync(ii+1) ⇒ race-free
    }

    // ---- per-block partials to scratch (coalesced STG, no atomics) ----
    float* dst = g_scratch + (size_t)blockIdx.x * OUTSZ + b * (OC * OD) + c * OD + odh * 8;
    ulonglong2 s0; s0.x = acc[0]; s0.y = acc[1];
    ulonglong2 s1; s1.x = acc[2]; s1.y = acc[3];
    ((ulonglong2*)dst)[0] = s0;
    ((ulonglong2*)dst)[1] = s1;
}

// Reduce: 160 blocks x 512 threads; warp = k-slice, lane = output element.
__global__ __launch_bounds__(512, 1) void caps_reduce_kernel(float* __restrict__ out) {
    __shared__ float red[16][32];
    const int lane = threadIdx.x & 31;
    const int ks   = threadIdx.x >> 5;         // 0..15
    const int j    = blockIdx.x * 32 + lane;   // output index (5120 total)

    const float* src = g_scratch + (size_t)ks * OUTSZ + j;
    float s = 0.f;
    #pragma unroll
    for (int k = 0; k < 9; k++)                // ks, ks+16, ..., ks+128
        s += __ldcg(src + (size_t)k * 16 * OUTSZ);

    red[ks][lane] = s;
    __syncthreads();
    if (ks == 0) {
        float acc = 0.f;
        #pragma unroll
        for (int q = 0; q < 16; q++) acc += red[q][lane];
        out[j] = acc;
    }
}

extern "C" void kernel_launch(void* const* d_in, const int* in_sizes, int n_in,
                              void* d_out, int out_size)
{
    const float* x = (const float*)d_in[0];
    const float* w = (const float*)d_in[1];
    if (n_in >= 2 && in_sizes[0] == IC * OC * ID * OD && in_sizes[1] == BATCH * IC * ID) {
        x = (const float*)d_in[1];
        w = (const float*)d_in[0];
    }
    float* out = (float*)d_out;

    caps_kernel<<<NBLK, THREADS>>>(x, w, out);
    caps_reduce_kernel<<<OUTSZ / 32, 512>>>(out);
}

// round 9
// speedup vs baseline: 1.2285x; 1.0851x over previous
#include <cuda_runtime.h>

#define IC 1152
#define OC 10
#define ID 8
#define OD 16
#define BATCH 32
#define NI 8
#define NBLK (IC / NI)     // 144
#define THREADS 640        // 20 warps: thread = (c, b, od_half)
#define OUTSZ (BATCH * OC * OD)   // 5120
#define WROW (OC * ID)     // 80 weight rows (of 16 floats) per i

typedef unsigned long long ull;

__device__ float g_scratch[NBLK * OUTSZ];   // per-block partial outputs

__device__ __forceinline__ ull ffma2(ull a, ull b, ull c) {
    ull d; asm("fma.rn.f32x2 %0, %1, %2, %3;" : "=l"(d) : "l"(a), "l"(b), "l"(c)); return d;
}
__device__ __forceinline__ ull fmul2(ull a, ull b) {
    ull d; asm("mul.rn.f32x2 %0, %1, %2;" : "=l"(d) : "l"(a), "l"(b)); return d;
}
__device__ __forceinline__ ull fadd2(ull a, ull b) {
    ull d; asm("add.rn.f32x2 %0, %1, %2;" : "=l"(d) : "l"(a), "l"(b)); return d;
}
__device__ __forceinline__ ull pack2(float x, float y) {
    ull u; asm("mov.b64 %0, {%1, %2};" : "=l"(u) : "f"(x), "f"(y)); return u;
}
__device__ __forceinline__ void unpack2(ull u, float& x, float& y) {
    asm("mov.b64 {%0, %1}, %2;" : "=f"(x), "=f"(y) : "l"(u));
}
__device__ __forceinline__ float frcp(float x) {
    float y; asm("rcp.approx.f32 %0, %1;" : "=f"(y) : "f"(x)); return y;
}
// full 16-od dot contribution for one d, as a 4-op chained ffma2 sequence
__device__ __forceinline__ ull dot4(ull h0, ull h1, ull h2, ull h3,
                                    ull w0, ull w1, ull w2, ull w3) {
    ull p = fmul2(h0, w0);
    p = ffma2(h1, w1, p);
    p = ffma2(h2, w2, p);
    p = ffma2(h3, w3, p);
    return p;
}

__global__ __launch_bounds__(THREADS, 1) void caps_kernel(
    const float* __restrict__ x, const float* __restrict__ w, float* __restrict__ out_unused)
{
    __shared__ __align__(16) float ws_sm[NI * OC * ID * OD];  // all 8 i's, 40KB
    __shared__ float wsum_sm[NI * WROW];
    __shared__ float xn_sm[NI][ID][BATCH + 1];                // padded transpose
    __shared__ float alpha_sm[2][OC * BATCH];

    const int t   = threadIdx.x;
    const int c   = t >> 6;          // output capsule: 2 warps per c
    const int b   = (t & 63) >> 1;   // batch
    const int odh = t & 1;           // od half
    const int i0  = blockIdx.x * NI;
    const bool evenGrp = (t & 32) == 0;   // warp parity == b-half membership

    // ==== stage ALL weights: thread t owns row (ii,c,d)=t; row-sum in-thread ====
    {
        const float4* wr = (const float4*)(w + ((size_t)i0 * WROW + t) * OD);
        float4 a0 = wr[0], a1 = wr[1], a2 = wr[2], a3 = wr[3];
        float tot = (a0.x + a0.y + a0.z + a0.w) + (a1.x + a1.y + a1.z + a1.w)
                  + (a2.x + a2.y + a2.z + a2.w) + (a3.x + a3.y + a3.z + a3.w);
        float r = frcp(tot);
        float4* dst = (float4*)(ws_sm + t * OD);
        float4 s0, s1, s2, s3;
        s0.x = a0.x * r; s0.y = a0.y * r; s0.z = a0.z * r; s0.w = a0.w * r;
        s1.x = a1.x * r; s1.y = a1.y * r; s1.z = a1.z * r; s1.w = a1.w * r;
        s2.x = a2.x * r; s2.y = a2.y * r; s2.z = a2.z * r; s2.w = a2.w * r;
        s3.x = a3.x * r; s3.y = a3.y * r; s3.z = a3.z * r; s3.w = a3.w * r;
        dst[0] = s0; dst[1] = s1; dst[2] = s2; dst[3] = s3;
        wsum_sm[t] = tot;
    }
    // ==== stage ALL x: t<512: thread = (b, q) with q = (ii, d-half) ====
    if (t < 512) {
        int bb = t >> 4, q = t & 15;
        float4 xv = *(const float4*)(x + (size_t)bb * (IC * ID) + (size_t)i0 * ID + q * 4);
        float ps  = xv.x + xv.y + xv.z + xv.w;
        float tot = ps + __shfl_xor_sync(0xffffffffu, ps, 1);
        float r = frcp(tot);
        int ii = q >> 1, dh = (q & 1) * 4;
        xn_sm[ii][dh + 0][bb] = xv.x * r;
        xn_sm[ii][dh + 1][bb] = xv.y * r;
        xn_sm[ii][dh + 2][bb] = xv.z * r;
        xn_sm[ii][dh + 3][bb] = xv.w * r;
    }
    __syncthreads();   // the only full-block barrier

    ull acc[4];
    #pragma unroll
    for (int j = 0; j < 4; j++) acc[j] = pack2(0.f, 0.f);

    #pragma unroll 1
    for (int ii = 0; ii < NI; ii++) {
        const int p = ii & 1;
        const float* wc = ws_sm + ii * (OC * ID * OD) + c * (ID * OD) + odh * 8;
        float xn[8];
        #pragma unroll
        for (int d = 0; d < 8; d++) xn[d] = xn_sm[ii][d][b];

        // ---- iteration 1: h1[o] = Σ_d xn[d]·ŵ[d,o]  (h0 uniform) ----
        ull h[4];
        {
            const ulonglong2* wr = (const ulonglong2*)wc;
            ulonglong2 wa = wr[0], wb2 = wr[1];
            ull xp = pack2(xn[0], xn[0]);
            h[0] = fmul2(xp, wa.x);
            h[1] = fmul2(xp, wa.y);
            h[2] = fmul2(xp, wb2.x);
            h[3] = fmul2(xp, wb2.y);
        }
        #pragma unroll
        for (int d = 1; d < 8; d++) {
            ull xp = pack2(xn[d], xn[d]);
            const ulonglong2* wr = (const ulonglong2*)(wc + d * 16);
            ulonglong2 wa = wr[0], wb2 = wr[1];
            h[0] = ffma2(xp, wa.x,  h[0]);
            h[1] = ffma2(xp, wa.y,  h[1]);
            h[2] = ffma2(xp, wb2.x, h[2]);
            h[3] = ffma2(xp, wb2.y, h[3]);
        }

        // ---- iterations 2..5, fused den/f passes (scale-invariant ⇒ no renorm) ----
        #pragma unroll 1
        for (int it = 0; it < 4; it++) {
            ull f[4];
            #pragma unroll
            for (int j = 0; j < 4; j++) f[j] = pack2(0.f, 0.f);
            #pragma unroll
            for (int d = 0; d < 8; d++) {
                const ulonglong2* wr = (const ulonglong2*)(wc + d * 16);
                ulonglong2 wa = wr[0], wb2 = wr[1];
                ull pp = dot4(h[0], h[1], h[2], h[3], wa.x, wa.y, wb2.x, wb2.y);
                float pa, pb; unpack2(pp, pa, pb);
                float hd  = pa + pb;
                float den = hd + __shfl_xor_sync(0xffffffffu, hd, 1);
                float xr  = xn[d] * frcp(den);
                ull xp = pack2(xr, xr);
                f[0] = ffma2(xp, wa.x,  f[0]);
                f[1] = ffma2(xp, wa.y,  f[1]);
                f[2] = ffma2(xp, wb2.x, f[2]);
                f[3] = ffma2(xp, wb2.y, f[3]);
            }
            #pragma unroll
            for (int j = 0; j < 4; j++) h[j] = fmul2(h[j], f[j]);
        }

        // ---- epilogue: alpha from final denominators (reconstruct folded in) ----
        float A = 0.f;
        #pragma unroll
        for (int d = 0; d < 8; d++) {
            const ulonglong2* wr = (const ulonglong2*)(wc + d * 16);
            ulonglong2 wa = wr[0], wb2 = wr[1];
            ull pp = dot4(h[0], h[1], h[2], h[3], wa.x, wa.y, wb2.x, wb2.y);
            float pa, pb; unpack2(pp, pa, pb);
            float hd  = pa + pb;
            float den = hd + __shfl_xor_sync(0xffffffffu, hd, 1);
            A = fmaf(xn[d] * wsum_sm[ii * WROW + c * 8 + d], den, A);
        }
        ull s2 = fadd2(fadd2(h[0], h[1]), fadd2(h[2], h[3]));
        float sa, sb; unpack2(s2, sa, sb);
        float shh = sa + sb;
        float Sh  = shh + __shfl_xor_sync(0xffffffffu, shh, 1);
        float rSh = frcp(Sh);
        float ar  = A * rSh;
        if (odh == 0) alpha_sm[p][c * BATCH + b] = ar;
        // split barrier: even-b data touched only by even warps, odd by odd
        if (evenGrp) { asm volatile("bar.sync 1, 320;" ::: "memory"); }
        else         { asm volatile("bar.sync 2, 320;" ::: "memory"); }
        float S = 0.f;
        #pragma unroll
        for (int cc = 0; cc < OC; cc++) S += alpha_sm[p][cc * BATCH + b];
        float coeff = ar * frcp(S) * rSh;
        ull cp = pack2(coeff, coeff);
        #pragma unroll
        for (int j = 0; j < 4; j++) acc[j] = ffma2(cp, h[j], acc[j]);
        // alpha_sm[p] rewritten at ii+2, after that group's barrier(ii+1) ⇒ race-free
    }

    // ---- per-block partials to scratch (coalesced STG, no atomics) ----
    float* dst = g_scratch + (size_t)blockIdx.x * OUTSZ + b * (OC * OD) + c * OD + odh * 8;
    ulonglong2 s0; s0.x = acc[0]; s0.y = acc[1];
    ulonglong2 s1; s1.x = acc[2]; s1.y = acc[3];
    ((ulonglong2*)dst)[0] = s0;
    ((ulonglong2*)dst)[1] = s1;
}

// Reduce: 160 blocks x 512 threads; warp = k-slice, lane = output element.
__global__ __launch_bounds__(512, 1) void caps_reduce_kernel(float* __restrict__ out) {
    __shared__ float red[16][32];
    const int lane = threadIdx.x & 31;
    const int ks   = threadIdx.x >> 5;         // 0..15
    const int j    = blockIdx.x * 32 + lane;   // output index (5120 total)

    const float* src = g_scratch + (size_t)ks * OUTSZ + j;
    float s = 0.f;
    #pragma unroll
    for (int k = 0; k < 9; k++)                // ks, ks+16, ..., ks+128
        s += __ldcg(src + (size_t)k * 16 * OUTSZ);

    red[ks][lane] = s;
    __syncthreads();
    if (ks == 0) {
        float acc = 0.f;
        #pragma unroll
        for (int q = 0; q < 16; q++) acc += red[q][lane];
        out[j] = acc;
    }
}

extern "C" void kernel_launch(void* const* d_in, const int* in_sizes, int n_in,
                              void* d_out, int out_size)
{
    const float* x = (const float*)d_in[0];
    const float* w = (const float*)d_in[1];
    if (n_in >= 2 && in_sizes[0] == IC * OC * ID * OD && in_sizes[1] == BATCH * IC * ID) {
        x = (const float*)d_in[1];
        w = (const float*)d_in[0];
    }
    float* out = (float*)d_out;

    caps_kernel<<<NBLK, THREADS>>>(x, w, out);
    caps_reduce_kernel<<<OUTSZ / 32, 512>>>(out);
}